// round 13
// baseline (speedup 1.0000x reference)
#include <cuda_runtime.h>
#include <cuda_fp16.h>

// CapsuleLayer dynamic routing, GB300 sm_103a.
// B=32, IN_CAPS=1152, P=64, NUM_CAPS=32, Q=64, NUM_ROUTING=3.
//
// hat[b,i,c,q] = sum_p x[b,i,p] * W[i,c,p,q]   (tf32 mma.sync, stored fp16)
// r0: c0 = softmax_c(bias) batch-independent -> S0 partials inside GEMM (fp32)
// r1: b1 = bias + <hat,v0>_q ; S1 = sum_i softmax_c(b1)*hat ; v1=squash(S1)
// r2: b2 = bias + <hat,v0+v1>_q ; S2 = ... ; out = squash(S2)
// All S sums via non-atomic per-block partials, reduced in squash kernels.

#define BB 32
#define IC 1152
#define PP 64
#define NC 32
#define QQ 64
#define HAT_ELEMS (BB * IC * NC * QQ)
#define SV (BB * NC * QQ)
#define NIBLK 36     // gemm i-blocks
#define NRBLK 64     // route i-blocks (IC / RICH)

// ---------------- device scratch ----------------
__device__ __align__(16) __half g_hat[HAT_ELEMS];      // 151 MB
__device__ __align__(16) float g_S0p[NIBLK * SV];      // 9.4 MB partials
__device__ __align__(16) float g_S1p[NRBLK * SV];      // 16.8 MB partials
__device__ __align__(16) float g_S2p[NRBLK * SV];      // 16.8 MB partials
__device__ __align__(16) float g_v0[SV];
__device__ __align__(16) float g_v01[SV];

// ---------------- helpers ----------------
__device__ __forceinline__ unsigned int fu(float f) { return __float_as_uint(f); }

__device__ __forceinline__ void cp16(const void* smem_dst, const void* gmem_src) {
    unsigned int s = (unsigned int)__cvta_generic_to_shared(smem_dst);
    asm volatile("cp.async.cg.shared.global [%0], [%1], 16;" :: "r"(s), "l"(gmem_src));
}
__device__ __forceinline__ void cp_commit() {
    asm volatile("cp.async.commit_group;");
}
template <int N>
__device__ __forceinline__ void cp_wait() {
    asm volatile("cp.async.wait_group %0;" :: "n"(N));
}

// tf32 m16n8k8: D += A*B. A row-major [16x8], B col-major [8x8], fp32 accum.
#define MMA_TF32(D, A, B0, B1)                                            \
    asm volatile(                                                          \
        "mma.sync.aligned.m16n8k8.row.col.f32.tf32.tf32.f32 "              \
        "{%0,%1,%2,%3},{%4,%5,%6,%7},{%8,%9},{%0,%1,%2,%3};"               \
        : "+f"((D)[0]), "+f"((D)[1]), "+f"((D)[2]), "+f"((D)[3])           \
        : "r"(fu((A)[0])), "r"(fu((A)[1])), "r"(fu((A)[2])), "r"(fu((A)[3])), \
          "r"(fu(B0)), "r"(fu(B1)))

// ---------------- GEMM (tf32): hat (fp16, staged) + S0 partials + fused c0 --
// Grid (16 cpairs, 36 iblocks), 128 threads (4 warps), 2 CTAs/SM.
#define ICH 32
#define WS_STRIDE 136     // 136 % 32 == 8 -> bank = 8k+n : conflict-free B reads
#define XS_STRIDE 68      // 68 % 32 == 4  -> bank = 4b+p : conflict-free A reads
#define HS_STRIDE 136     // halfs per staging row
#define WS_FLOATS (PP * WS_STRIDE)   // 8704
#define XS_FLOATS (BB * XS_STRIDE)   // 2176
#define HS_FLOATS (BB * HS_STRIDE / 2)
#define GEMM_SMEM_BYTES ((2 * WS_FLOATS + 2 * XS_FLOATS + HS_FLOATS) * 4)  // 95744

__device__ __forceinline__ void gemm_prefetch(float* ws, float* xs,
                                              const float* __restrict__ x,
                                              const float* __restrict__ W,
                                              int i, int cpair, int tid) {
    const float4* wsrc = (const float4*)(W + ((size_t)i * NC + cpair * 2) * (PP * QQ));
#pragma unroll
    for (int k = 0; k < 16; k++) {
        int j4 = tid + 128 * k;          // [0,2048)
        int cl = j4 >> 10;
        int p = (j4 >> 4) & 63;
        int q4 = j4 & 15;
        cp16(ws + p * WS_STRIDE + cl * QQ + q4 * 4, wsrc + j4);
    }
#pragma unroll
    for (int k = 0; k < 4; k++) {
        int j = tid + 128 * k;           // [0,512)
        int b = j >> 4;
        int p4 = j & 15;
        cp16(xs + b * XS_STRIDE + p4 * 4, x + ((size_t)b * IC + i) * PP + p4 * 4);
    }
}

__global__ __launch_bounds__(128, 2) void gemm_kernel(const float* __restrict__ x,
                                                      const float* __restrict__ W,
                                                      const float* __restrict__ bias) {
    extern __shared__ __align__(16) float smem[];
    __shared__ float c0sh[ICH][2];
    float* ws0 = smem;
    float* ws1 = smem + WS_FLOATS;
    float* xs0 = smem + 2 * WS_FLOATS;
    float* xs1 = xs0 + XS_FLOATS;
    __half* stag = (__half*)(xs1 + XS_FLOATS);   // [32 rows][136 halfs]

    int tid = threadIdx.x;
    int warp = tid >> 5;
    int lane = tid & 31;
    int g = lane >> 2;      // 0..7
    int tig = lane & 3;     // 0..3
    int cpair = blockIdx.x;
    int iblk = blockIdx.y;
    int i0 = iblk * ICH;
    int n0 = warp * 32;               // slice within 128-wide N
    int cl = warp >> 1;               // capsule-local
    int c = cpair * 2 + cl;
    int qn = n0 & 63;
    int qbase = qn + tig * 2;

    gemm_prefetch(ws0, xs0, x, W, i0, cpair, tid);
    cp_commit();

    // fused c0 = softmax_c(bias) for this CTA's rows (overlaps first loads)
    if (tid < ICH) {
        const float* bp = bias + (size_t)(i0 + tid) * NC;
        float m = -1e30f;
#pragma unroll 8
        for (int cc = 0; cc < NC; cc++) m = fmaxf(m, bp[cc]);
        float s = 0.f;
#pragma unroll 8
        for (int cc = 0; cc < NC; cc++) s += __expf(bp[cc] - m);
        float inv = 1.f / s;
        c0sh[tid][0] = __expf(bp[cpair * 2 + 0] - m) * inv;
        c0sh[tid][1] = __expf(bp[cpair * 2 + 1] - m) * inv;
    }

    float s0[2][4][4];
#pragma unroll
    for (int mt = 0; mt < 2; mt++)
#pragma unroll
        for (int nt = 0; nt < 4; nt++)
#pragma unroll
            for (int j = 0; j < 4; j++) s0[mt][nt][j] = 0.f;

    for (int ii = 0; ii < ICH; ii++) {
        int i = i0 + ii;
        cp_wait<0>();
        __syncthreads();
        if (ii + 1 < ICH) {
            float* wsn = ((ii + 1) & 1) ? ws1 : ws0;
            float* xsn = ((ii + 1) & 1) ? xs1 : xs0;
            gemm_prefetch(wsn, xsn, x, W, i + 1, cpair, tid);
        }
        cp_commit();
        const float* wsc = (ii & 1) ? ws1 : ws0;
        const float* xsc = (ii & 1) ? xs1 : xs0;

        float d[2][4][4];
#pragma unroll
        for (int mt = 0; mt < 2; mt++)
#pragma unroll
            for (int nt = 0; nt < 4; nt++)
#pragma unroll
                for (int j = 0; j < 4; j++) d[mt][nt][j] = 0.f;

#pragma unroll
        for (int ks = 0; ks < 8; ks++) {
            float a[2][4];
#pragma unroll
            for (int mt = 0; mt < 2; mt++) {
                int base = (mt * 16 + g) * XS_STRIDE + ks * 8 + tig;
                a[mt][0] = xsc[base];
                a[mt][1] = xsc[base + 8 * XS_STRIDE];
                a[mt][2] = xsc[base + 4];
                a[mt][3] = xsc[base + 8 * XS_STRIDE + 4];
            }
#pragma unroll
            for (int nt = 0; nt < 4; nt++) {
                int bb = (ks * 8 + tig) * WS_STRIDE + n0 + nt * 8 + g;
                float b0 = wsc[bb];
                float b1 = wsc[bb + 4 * WS_STRIDE];
                MMA_TF32(d[0][nt], a[0], b0, b1);
                MMA_TF32(d[1][nt], a[1], b0, b1);
            }
        }

        // S0 fused accumulation + stage hat tile in smem (conflict-free STS)
        float wgt = c0sh[ii][cl];
#pragma unroll
        for (int mt = 0; mt < 2; mt++) {
#pragma unroll
            for (int nt = 0; nt < 4; nt++) {
                int row0 = mt * 16 + g;
                int ncol = n0 + nt * 8 + tig * 2;
                *(__half2*)(stag + row0 * HS_STRIDE + ncol) =
                    __floats2half2_rn(d[mt][nt][0], d[mt][nt][1]);
                *(__half2*)(stag + (row0 + 8) * HS_STRIDE + ncol) =
                    __floats2half2_rn(d[mt][nt][2], d[mt][nt][3]);
#pragma unroll
                for (int j = 0; j < 4; j++)
                    s0[mt][nt][j] = fmaf(wgt, d[mt][nt][j], s0[mt][nt][j]);
            }
        }
        __syncthreads();

        // coalesced writeback: staging row b (n 0..127) -> 256B contiguous gmem
        {
            int c16 = lane & 15;
            int rsub = lane >> 4;
#pragma unroll
            for (int k = 0; k < 4; k++) {
                int r = warp * 8 + k * 2 + rsub;
                uint4 v = *(const uint4*)(stag + r * HS_STRIDE + c16 * 8);
                __half* dst = g_hat + (((size_t)r * IC + i) * NC + cpair * 2) * QQ
                              + c16 * 8;
                *(uint4*)dst = v;
            }
        }
    }

    // non-atomic per-iblock S0 partials
    float* sp = g_S0p + (size_t)iblk * SV;
#pragma unroll
    for (int mt = 0; mt < 2; mt++) {
#pragma unroll
        for (int nt = 0; nt < 4; nt++) {
            int q = qbase + nt * 8;
            int b0r = mt * 16 + g;
            *(float2*)(sp + ((size_t)b0r * NC + c) * QQ + q) =
                make_float2(s0[mt][nt][0], s0[mt][nt][1]);
            *(float2*)(sp + ((size_t)(b0r + 8) * NC + c) * QQ + q) =
                make_float2(s0[mt][nt][2], s0[mt][nt][3]);
        }
    }
}

// ---------------- routing pass (rounds 1, 2) -------------------------------
// RICH=18 tiles/CTA in 6 groups of 3, 3-stage cp.async pipeline (wait<1>).
// Thread (c=tid>>3, jj=tid&7) owns hat [c*64+jj*8, +8) as packed half2 regs.
// Non-atomic per-iblock S partials. 5 CTAs/SM (37.6 KB smem, <=51 regs).
#define RICH 18
#define IIB 3
#define NGRP (RICH / IIB)                          // 6
#define RT_GRP_HALFS (IIB * NC * QQ)               // 6144 halfs = 12 KB
#define RT_SMEM_BYTES (3 * RT_GRP_HALFS * 2 + 2 * IIB * NC * 4)  // 37632

__global__ __launch_bounds__(256, 5) void route_kernel(int round,
                                                       const float* __restrict__ bias) {
    extern __shared__ __align__(16) char rsm[];
    __half* hb = (__half*)rsm;                              // 3 x 12 KB
    float* tb = (float*)(rsm + 3 * RT_GRP_HALFS * 2);       // IIB*NC
    float* csh = tb + IIB * NC;                             // IIB*NC

    const float* vin = (round == 1) ? g_v0 : g_v01;
    float* Sp = (round == 1) ? g_S1p : g_S2p;

    int tid = threadIdx.x;
    int lane = tid & 31;
    int warp = tid >> 5;
    int b = blockIdx.y;
    int iblk = blockIdx.x;
    int i0 = iblk * RICH;
    int c = tid >> 3;       // owned capsule
    int jj = tid & 7;       // q-segment within capsule

    // loop-invariant v slice -> registers (8 floats)
    float vreg[8];
    *(float4*)&vreg[0] = *(const float4*)(vin + b * (NC * QQ) + tid * 8);
    *(float4*)&vreg[4] = *(const float4*)(vin + b * (NC * QQ) + tid * 8 + 4);

    const __half* hsrc = g_hat + (size_t)b * IC * (NC * QQ) + tid * 8;

    // prefetch groups 0 and 1 (separate commit groups)
#pragma unroll
    for (int t = 0; t < IIB; t++)
        cp16(hb + t * (NC * QQ) + tid * 8, hsrc + (size_t)(i0 + t) * (NC * QQ));
    cp_commit();
#pragma unroll
    for (int t = 0; t < IIB; t++)
        cp16(hb + RT_GRP_HALFS + t * (NC * QQ) + tid * 8,
             hsrc + (size_t)(i0 + IIB + t) * (NC * QQ));
    cp_commit();

    float racc[8];
#pragma unroll
    for (int j = 0; j < 8; j++) racc[j] = 0.f;

    for (int gg = 0; gg < NGRP; gg++) {
        cp_wait<1>();   // group gg ready; gg+1 may still be in flight
        __syncthreads();
        if (gg + 2 < NGRP) {
            __half* dst = hb + ((gg + 2) % 3) * RT_GRP_HALFS;
            int ib = i0 + (gg + 2) * IIB;
#pragma unroll
            for (int t = 0; t < IIB; t++)
                cp16(dst + t * (NC * QQ) + tid * 8,
                     hsrc + (size_t)(ib + t) * (NC * QQ));
        }
        cp_commit();    // empty group at tail keeps wait<1> semantics

        const __half* hbuf = hb + (gg % 3) * RT_GRP_HALFS;

        // phase 1: single LDS.128 per tile (packed half2 regs); raw logits
        uint4 hv[IIB];
#pragma unroll
        for (int t = 0; t < IIB; t++)
            hv[t] = *(const uint4*)(hbuf + t * (NC * QQ) + tid * 8);
#pragma unroll
        for (int t = 0; t < IIB; t++) {
            const __half2* hp = (const __half2*)&hv[t];
            float s = 0.f;
#pragma unroll
            for (int j = 0; j < 4; j++) {
                float2 f = __half22float2(hp[j]);
                s = fmaf(f.x, vreg[2 * j], s);
                s = fmaf(f.y, vreg[2 * j + 1], s);
            }
            s += __shfl_down_sync(0xffffffffu, s, 4);
            s += __shfl_down_sync(0xffffffffu, s, 2);
            s += __shfl_down_sync(0xffffffffu, s, 1);
            if (jj == 0) tb[t * NC + c] = s;
        }
        __syncthreads();

        // phase 2: warp w < IIB -> softmax of tile w (lane <-> capsule);
        // bias added here (coalesced LDG, L2-hot across the 32 b-CTAs)
        if (warp < IIB) {
            int i = i0 + gg * IIB + warp;
            float t_ = tb[warp * NC + lane] + __ldg(bias + (size_t)i * NC + lane);
            float m = t_;
#pragma unroll
            for (int o = 16; o > 0; o >>= 1)
                m = fmaxf(m, __shfl_xor_sync(0xffffffffu, m, o));
            float e = __expf(t_ - m);
            float se = e;
#pragma unroll
            for (int o = 16; o > 0; o >>= 1)
                se += __shfl_xor_sync(0xffffffffu, se, o);
            csh[warp * NC + lane] = e / se;
        }
        __syncthreads();

        // phase 3: weighted accumulation (csh read is an 8-thread broadcast)
#pragma unroll
        for (int t = 0; t < IIB; t++) {
            float wc = csh[t * NC + c];
            const __half2* hp = (const __half2*)&hv[t];
#pragma unroll
            for (int j = 0; j < 4; j++) {
                float2 f = __half22float2(hp[j]);
                racc[2 * j] = fmaf(wc, f.x, racc[2 * j]);
                racc[2 * j + 1] = fmaf(wc, f.y, racc[2 * j + 1]);
            }
        }
    }

    // non-atomic per-iblock partials (coalesced float4 stores)
    float* sp = Sp + ((size_t)iblk * BB + b) * (NC * QQ) + tid * 8;
    *(float4*)sp = make_float4(racc[0], racc[1], racc[2], racc[3]);
    *(float4*)(sp + 4) = make_float4(racc[4], racc[5], racc[6], racc[7]);
}

// ---------------- squash ----------------
// squash0: reduce S0 partials + squash -> v0
__global__ void squash0_kernel() {
    int vec = blockIdx.x;  // b*NC + c
    int lane = threadIdx.x;
    float x0 = 0.f, x1 = 0.f;
#pragma unroll 4
    for (int ib = 0; ib < NIBLK; ib++) {
        x0 += g_S0p[(size_t)ib * SV + vec * QQ + lane];
        x1 += g_S0p[(size_t)ib * SV + vec * QQ + 32 + lane];
    }
    float ss = x0 * x0 + x1 * x1;
#pragma unroll
    for (int o = 16; o > 0; o >>= 1)
        ss += __shfl_xor_sync(0xffffffffu, ss, o);
    float sc = (ss > 0.f) ? (ss / (1.f + ss)) * rsqrtf(ss) : 0.f;
    g_v0[vec * QQ + lane] = sc * x0;
    g_v0[vec * QQ + 32 + lane] = sc * x1;
}

// mode 1: v01 = v0 + squash(sum S1p); mode 2: out = squash(sum S2p)
__global__ void squash_kernel(int mode, float* __restrict__ dout) {
    const float* Sp = (mode == 1) ? g_S1p : g_S2p;
    int vec = blockIdx.x;          // b*NC + c
    int lane = threadIdx.x;
    int b = vec >> 5;
    int cq = (vec & 31) * QQ;
    float x0 = 0.f, x1 = 0.f;
#pragma unroll 8
    for (int ib = 0; ib < NRBLK; ib++) {
        const float* p = Sp + ((size_t)ib * BB + b) * (NC * QQ) + cq;
        x0 += p[lane];
        x1 += p[lane + 32];
    }
    float ss = x0 * x0 + x1 * x1;
#pragma unroll
    for (int o = 16; o > 0; o >>= 1)
        ss += __shfl_xor_sync(0xffffffffu, ss, o);
    float sc = (ss > 0.f) ? (ss / (1.f + ss)) * rsqrtf(ss) : 0.f;
    float o0 = sc * x0, o1 = sc * x1;
    if (mode == 1) {
        g_v01[vec * QQ + lane] = g_v0[vec * QQ + lane] + o0;
        g_v01[vec * QQ + 32 + lane] = g_v0[vec * QQ + 32 + lane] + o1;
    } else {
        dout[vec * QQ + lane] = o0;
        dout[vec * QQ + 32 + lane] = o1;
    }
}

// ---------------- launch ----------------
extern "C" void kernel_launch(void* const* d_in, const int* in_sizes, int n_in,
                              void* d_out, int out_size) {
    const float* x = (const float*)d_in[0];     // [32,1152,64]
    const float* W = (const float*)d_in[1];     // [1152,32,64,64]
    const float* bias = (const float*)d_in[2];  // [1,1152,32,1]
    float* out = (float*)d_out;                 // [32,32,64]

    static int smem_set = 0;
    if (!smem_set) {
        cudaFuncSetAttribute(gemm_kernel, cudaFuncAttributeMaxDynamicSharedMemorySize,
                             GEMM_SMEM_BYTES);
        cudaFuncSetAttribute(route_kernel, cudaFuncAttributeMaxDynamicSharedMemorySize,
                             RT_SMEM_BYTES);
        smem_set = 1;
    }

    gemm_kernel<<<dim3(NC / 2, NIBLK), 128, GEMM_SMEM_BYTES>>>(x, W, bias);
    squash0_kernel<<<BB * NC, 32>>>();
    route_kernel<<<dim3(NRBLK, BB), 256, RT_SMEM_BYTES>>>(1, bias);
    squash_kernel<<<BB * NC, 32>>>(1, out);
    route_kernel<<<dim3(NRBLK, BB), 256, RT_SMEM_BYTES>>>(2, bias);
    squash_kernel<<<BB * NC, 32>>>(2, out);
}

// round 14
// speedup vs baseline: 1.0376x; 1.0376x over previous
#include <cuda_runtime.h>
#include <cuda_fp16.h>

// CapsuleLayer dynamic routing, GB300 sm_103a.
// B=32, IN_CAPS=1152, P=64, NUM_CAPS=32, Q=64, NUM_ROUTING=3.
//
// hat[b,i,c,q] = sum_p x[b,i,p] * W[i,c,p,q]   (tf32 mma.sync, stored fp16)
// r0: c0 = softmax_c(bias) batch-independent -> S0 partials inside GEMM (fp32)
// r1: b1 = bias + <hat,v0>_q ; S1 = sum_i softmax_c(b1)*hat ; v1=squash(S1)
// r2: b2 = bias + <hat,v0+v1>_q ; S2 = ... ; out = squash(S2)
// All S sums via non-atomic per-block partials, reduced in parallel squash kernels.

#define BB 32
#define IC 1152
#define PP 64
#define NC 32
#define QQ 64
#define HAT_ELEMS (BB * IC * NC * QQ)
#define SV (BB * NC * QQ)
#define NIBLK 36     // gemm i-blocks
#define NRBLK 64     // route i-blocks (IC / RICH)

// ---------------- device scratch ----------------
__device__ __align__(16) __half g_hat[HAT_ELEMS];      // 151 MB
__device__ __align__(16) float g_S0p[NIBLK * SV];      // 9.4 MB partials
__device__ __align__(16) float g_S1p[NRBLK * SV];      // 16.8 MB partials
__device__ __align__(16) float g_S2p[NRBLK * SV];      // 16.8 MB partials
__device__ __align__(16) float g_v0[SV];
__device__ __align__(16) float g_v01[SV];

// ---------------- helpers ----------------
__device__ __forceinline__ unsigned int fu(float f) { return __float_as_uint(f); }

__device__ __forceinline__ void cp16(const void* smem_dst, const void* gmem_src) {
    unsigned int s = (unsigned int)__cvta_generic_to_shared(smem_dst);
    asm volatile("cp.async.cg.shared.global [%0], [%1], 16;" :: "r"(s), "l"(gmem_src));
}
__device__ __forceinline__ void cp_commit() {
    asm volatile("cp.async.commit_group;");
}
template <int N>
__device__ __forceinline__ void cp_wait() {
    asm volatile("cp.async.wait_group %0;" :: "n"(N));
}

// tf32 m16n8k8: D += A*B. A row-major [16x8], B col-major [8x8], fp32 accum.
#define MMA_TF32(D, A, B0, B1)                                            \
    asm volatile(                                                          \
        "mma.sync.aligned.m16n8k8.row.col.f32.tf32.tf32.f32 "              \
        "{%0,%1,%2,%3},{%4,%5,%6,%7},{%8,%9},{%0,%1,%2,%3};"               \
        : "+f"((D)[0]), "+f"((D)[1]), "+f"((D)[2]), "+f"((D)[3])           \
        : "r"(fu((A)[0])), "r"(fu((A)[1])), "r"(fu((A)[2])), "r"(fu((A)[3])), \
          "r"(fu(B0)), "r"(fu(B1)))

// ---------------- GEMM (tf32): hat (fp16, staged) + S0 partials + fused c0 --
// Grid (16 cpairs, 36 iblocks), 128 threads (4 warps), 2 CTAs/SM.
#define ICH 32
#define WS_STRIDE 136     // 136 % 32 == 8 -> bank = 8k+n : conflict-free B reads
#define XS_STRIDE 68      // 68 % 32 == 4  -> bank = 4b+p : conflict-free A reads
#define HS_STRIDE 136     // halfs per staging row
#define WS_FLOATS (PP * WS_STRIDE)   // 8704
#define XS_FLOATS (BB * XS_STRIDE)   // 2176
#define HS_FLOATS (BB * HS_STRIDE / 2)
#define GEMM_SMEM_BYTES ((2 * WS_FLOATS + 2 * XS_FLOATS + HS_FLOATS) * 4)  // 95744

__device__ __forceinline__ void gemm_prefetch(float* ws, float* xs,
                                              const float* __restrict__ x,
                                              const float* __restrict__ W,
                                              int i, int cpair, int tid) {
    const float4* wsrc = (const float4*)(W + ((size_t)i * NC + cpair * 2) * (PP * QQ));
#pragma unroll
    for (int k = 0; k < 16; k++) {
        int j4 = tid + 128 * k;          // [0,2048)
        int cl = j4 >> 10;
        int p = (j4 >> 4) & 63;
        int q4 = j4 & 15;
        cp16(ws + p * WS_STRIDE + cl * QQ + q4 * 4, wsrc + j4);
    }
#pragma unroll
    for (int k = 0; k < 4; k++) {
        int j = tid + 128 * k;           // [0,512)
        int b = j >> 4;
        int p4 = j & 15;
        cp16(xs + b * XS_STRIDE + p4 * 4, x + ((size_t)b * IC + i) * PP + p4 * 4);
    }
}

__global__ __launch_bounds__(128, 2) void gemm_kernel(const float* __restrict__ x,
                                                      const float* __restrict__ W,
                                                      const float* __restrict__ bias) {
    extern __shared__ __align__(16) float smem[];
    __shared__ float c0sh[ICH][2];
    float* ws0 = smem;
    float* ws1 = smem + WS_FLOATS;
    float* xs0 = smem + 2 * WS_FLOATS;
    float* xs1 = xs0 + XS_FLOATS;
    __half* stag = (__half*)(xs1 + XS_FLOATS);   // [32 rows][136 halfs]

    int tid = threadIdx.x;
    int warp = tid >> 5;
    int lane = tid & 31;
    int g = lane >> 2;      // 0..7
    int tig = lane & 3;     // 0..3
    int cpair = blockIdx.x;
    int iblk = blockIdx.y;
    int i0 = iblk * ICH;
    int n0 = warp * 32;               // slice within 128-wide N
    int cl = warp >> 1;               // capsule-local
    int c = cpair * 2 + cl;
    int qn = n0 & 63;
    int qbase = qn + tig * 2;

    gemm_prefetch(ws0, xs0, x, W, i0, cpair, tid);
    cp_commit();

    // fused c0 = softmax_c(bias) for this CTA's rows (overlaps first loads)
    if (tid < ICH) {
        const float* bp = bias + (size_t)(i0 + tid) * NC;
        float m = -1e30f;
#pragma unroll 8
        for (int cc = 0; cc < NC; cc++) m = fmaxf(m, bp[cc]);
        float s = 0.f;
#pragma unroll 8
        for (int cc = 0; cc < NC; cc++) s += __expf(bp[cc] - m);
        float inv = 1.f / s;
        c0sh[tid][0] = __expf(bp[cpair * 2 + 0] - m) * inv;
        c0sh[tid][1] = __expf(bp[cpair * 2 + 1] - m) * inv;
    }

    float s0[2][4][4];
#pragma unroll
    for (int mt = 0; mt < 2; mt++)
#pragma unroll
        for (int nt = 0; nt < 4; nt++)
#pragma unroll
            for (int j = 0; j < 4; j++) s0[mt][nt][j] = 0.f;

    for (int ii = 0; ii < ICH; ii++) {
        int i = i0 + ii;
        cp_wait<0>();
        __syncthreads();
        if (ii + 1 < ICH) {
            float* wsn = ((ii + 1) & 1) ? ws1 : ws0;
            float* xsn = ((ii + 1) & 1) ? xs1 : xs0;
            gemm_prefetch(wsn, xsn, x, W, i + 1, cpair, tid);
        }
        cp_commit();
        const float* wsc = (ii & 1) ? ws1 : ws0;
        const float* xsc = (ii & 1) ? xs1 : xs0;

        float d[2][4][4];
#pragma unroll
        for (int mt = 0; mt < 2; mt++)
#pragma unroll
            for (int nt = 0; nt < 4; nt++)
#pragma unroll
                for (int j = 0; j < 4; j++) d[mt][nt][j] = 0.f;

#pragma unroll
        for (int ks = 0; ks < 8; ks++) {
            float a[2][4];
#pragma unroll
            for (int mt = 0; mt < 2; mt++) {
                int base = (mt * 16 + g) * XS_STRIDE + ks * 8 + tig;
                a[mt][0] = xsc[base];
                a[mt][1] = xsc[base + 8 * XS_STRIDE];
                a[mt][2] = xsc[base + 4];
                a[mt][3] = xsc[base + 8 * XS_STRIDE + 4];
            }
#pragma unroll
            for (int nt = 0; nt < 4; nt++) {
                int bb = (ks * 8 + tig) * WS_STRIDE + n0 + nt * 8 + g;
                float b0 = wsc[bb];
                float b1 = wsc[bb + 4 * WS_STRIDE];
                MMA_TF32(d[0][nt], a[0], b0, b1);
                MMA_TF32(d[1][nt], a[1], b0, b1);
            }
        }

        // S0 fused accumulation + stage hat tile in smem (conflict-free STS)
        float wgt = c0sh[ii][cl];
#pragma unroll
        for (int mt = 0; mt < 2; mt++) {
#pragma unroll
            for (int nt = 0; nt < 4; nt++) {
                int row0 = mt * 16 + g;
                int ncol = n0 + nt * 8 + tig * 2;
                *(__half2*)(stag + row0 * HS_STRIDE + ncol) =
                    __floats2half2_rn(d[mt][nt][0], d[mt][nt][1]);
                *(__half2*)(stag + (row0 + 8) * HS_STRIDE + ncol) =
                    __floats2half2_rn(d[mt][nt][2], d[mt][nt][3]);
#pragma unroll
                for (int j = 0; j < 4; j++)
                    s0[mt][nt][j] = fmaf(wgt, d[mt][nt][j], s0[mt][nt][j]);
            }
        }
        __syncthreads();

        // coalesced writeback: staging row b (n 0..127) -> 256B contiguous gmem
        {
            int c16 = lane & 15;
            int rsub = lane >> 4;
#pragma unroll
            for (int k = 0; k < 4; k++) {
                int r = warp * 8 + k * 2 + rsub;
                uint4 v = *(const uint4*)(stag + r * HS_STRIDE + c16 * 8);
                __half* dst = g_hat + (((size_t)r * IC + i) * NC + cpair * 2) * QQ
                              + c16 * 8;
                *(uint4*)dst = v;
            }
        }
    }

    // non-atomic per-iblock S0 partials
    float* sp = g_S0p + (size_t)iblk * SV;
#pragma unroll
    for (int mt = 0; mt < 2; mt++) {
#pragma unroll
        for (int nt = 0; nt < 4; nt++) {
            int q = qbase + nt * 8;
            int b0r = mt * 16 + g;
            *(float2*)(sp + ((size_t)b0r * NC + c) * QQ + q) =
                make_float2(s0[mt][nt][0], s0[mt][nt][1]);
            *(float2*)(sp + ((size_t)(b0r + 8) * NC + c) * QQ + q) =
                make_float2(s0[mt][nt][2], s0[mt][nt][3]);
        }
    }
}

// ---------------- routing pass (rounds 1, 2) -------------------------------
// RICH=18 tiles/CTA in 6 groups of 3, 3-stage cp.async pipeline (wait<1>).
// Thread (c=tid>>3, jj=tid&7) owns hat [c*64+jj*8, +8) as packed half2 regs.
// bias preloaded to smem (off the critical softmax path). 5 CTAs/SM.
#define RICH 18
#define IIB 3
#define NGRP (RICH / IIB)                          // 6
#define RT_GRP_HALFS (IIB * NC * QQ)               // 6144 halfs = 12 KB
#define RT_SMEM_BYTES (3 * RT_GRP_HALFS * 2 + 2 * IIB * NC * 4 + RICH * NC * 4)

__global__ __launch_bounds__(256, 5) void route_kernel(int round,
                                                       const float* __restrict__ bias) {
    extern __shared__ __align__(16) char rsm[];
    __half* hb = (__half*)rsm;                              // 3 x 12 KB
    float* tb = (float*)(rsm + 3 * RT_GRP_HALFS * 2);       // IIB*NC
    float* csh = tb + IIB * NC;                             // IIB*NC
    float* bsh = csh + IIB * NC;                            // RICH*NC

    const float* vin = (round == 1) ? g_v0 : g_v01;
    float* Sp = (round == 1) ? g_S1p : g_S2p;

    int tid = threadIdx.x;
    int lane = tid & 31;
    int warp = tid >> 5;
    int b = blockIdx.y;
    int iblk = blockIdx.x;
    int i0 = iblk * RICH;
    int c = tid >> 3;       // owned capsule
    int jj = tid & 7;       // q-segment within capsule

    // loop-invariant v slice -> registers (8 floats)
    float vreg[8];
    *(float4*)&vreg[0] = *(const float4*)(vin + b * (NC * QQ) + tid * 8);
    *(float4*)&vreg[4] = *(const float4*)(vin + b * (NC * QQ) + tid * 8 + 4);

    // bias table preloaded off the critical path
    for (int j = tid; j < RICH * NC; j += 256) bsh[j] = bias[i0 * NC + j];

    const __half* hsrc = g_hat + (size_t)b * IC * (NC * QQ) + tid * 8;

    // prefetch groups 0 and 1 (separate commit groups)
#pragma unroll
    for (int t = 0; t < IIB; t++)
        cp16(hb + t * (NC * QQ) + tid * 8, hsrc + (size_t)(i0 + t) * (NC * QQ));
    cp_commit();
#pragma unroll
    for (int t = 0; t < IIB; t++)
        cp16(hb + RT_GRP_HALFS + t * (NC * QQ) + tid * 8,
             hsrc + (size_t)(i0 + IIB + t) * (NC * QQ));
    cp_commit();

    float racc[8];
#pragma unroll
    for (int j = 0; j < 8; j++) racc[j] = 0.f;

    for (int gg = 0; gg < NGRP; gg++) {
        cp_wait<1>();   // group gg ready; gg+1 may still be in flight
        __syncthreads();
        if (gg + 2 < NGRP) {
            __half* dst = hb + ((gg + 2) % 3) * RT_GRP_HALFS;
            int ib = i0 + (gg + 2) * IIB;
#pragma unroll
            for (int t = 0; t < IIB; t++)
                cp16(dst + t * (NC * QQ) + tid * 8,
                     hsrc + (size_t)(ib + t) * (NC * QQ));
        }
        cp_commit();    // empty group at tail keeps wait<1> semantics

        const __half* hbuf = hb + (gg % 3) * RT_GRP_HALFS;

        // phase 1: single LDS.128 per tile (packed half2 regs); logits
        uint4 hv[IIB];
#pragma unroll
        for (int t = 0; t < IIB; t++)
            hv[t] = *(const uint4*)(hbuf + t * (NC * QQ) + tid * 8);
#pragma unroll
        for (int t = 0; t < IIB; t++) {
            const __half2* hp = (const __half2*)&hv[t];
            float s = 0.f;
#pragma unroll
            for (int j = 0; j < 4; j++) {
                float2 f = __half22float2(hp[j]);
                s = fmaf(f.x, vreg[2 * j], s);
                s = fmaf(f.y, vreg[2 * j + 1], s);
            }
            s += __shfl_down_sync(0xffffffffu, s, 4);
            s += __shfl_down_sync(0xffffffffu, s, 2);
            s += __shfl_down_sync(0xffffffffu, s, 1);
            if (jj == 0) tb[t * NC + c] = s + bsh[(gg * IIB + t) * NC + c];
        }
        __syncthreads();

        // phase 2: warp w < IIB -> softmax of tile w (lane <-> capsule)
        if (warp < IIB) {
            float t_ = tb[warp * NC + lane];
            float m = t_;
#pragma unroll
            for (int o = 16; o > 0; o >>= 1)
                m = fmaxf(m, __shfl_xor_sync(0xffffffffu, m, o));
            float e = __expf(t_ - m);
            float se = e;
#pragma unroll
            for (int o = 16; o > 0; o >>= 1)
                se += __shfl_xor_sync(0xffffffffu, se, o);
            csh[warp * NC + lane] = e / se;
        }
        __syncthreads();

        // phase 3: weighted accumulation (csh read is an 8-thread broadcast)
#pragma unroll
        for (int t = 0; t < IIB; t++) {
            float wc = csh[t * NC + c];
            const __half2* hp = (const __half2*)&hv[t];
#pragma unroll
            for (int j = 0; j < 4; j++) {
                float2 f = __half22float2(hp[j]);
                racc[2 * j] = fmaf(wc, f.x, racc[2 * j]);
                racc[2 * j + 1] = fmaf(wc, f.y, racc[2 * j + 1]);
            }
        }
    }

    // non-atomic per-iblock partials (coalesced float4 stores)
    float* sp = Sp + ((size_t)iblk * BB + b) * (NC * QQ) + tid * 8;
    *(float4*)sp = make_float4(racc[0], racc[1], racc[2], racc[3]);
    *(float4*)(sp + 4) = make_float4(racc[4], racc[5], racc[6], racc[7]);
}

// ---------------- fused parallel reduce + squash ----------------
// Grid 1024 (one block per vec = b*NC+c), 256 threads.
// Thread (sl=t>>6, q=t&63) sums its partial slice; smem tree; warp 0 squashes.
// mode 0: S0p(36) -> v0 ; mode 1: S1p(64) -> v01 ; mode 2: S2p(64) -> out
__global__ __launch_bounds__(256) void reduce_squash_kernel(int mode,
                                                            float* __restrict__ dout) {
    __shared__ float red[4][QQ];
    int vec = blockIdx.x;
    int t = threadIdx.x;
    int q = t & 63, sl = t >> 6;
    int b = vec >> 5;
    int cq = (vec & 31) * QQ;

    float acc = 0.f;
    if (mode == 0) {
        // 36 partials: slices 9,9,9,9 ; layout ib*SV + vec*64 + q
#pragma unroll
        for (int k = 0; k < 9; k++) {
            int ib = sl * 9 + k;
            acc += g_S0p[(size_t)ib * SV + (size_t)vec * QQ + q];
        }
    } else {
        const float* Sp = (mode == 1) ? g_S1p : g_S2p;
        // 64 partials: slices of 16 ; layout (ib*BB+b)*2048 + cq + q
#pragma unroll
        for (int k = 0; k < 16; k++) {
            int ib = sl * 16 + k;
            acc += Sp[((size_t)ib * BB + b) * (NC * QQ) + cq + q];
        }
    }
    red[sl][q] = acc;
    __syncthreads();

    if (t < 32) {
        float x0 = red[0][t] + red[1][t] + red[2][t] + red[3][t];
        float x1 = red[0][t + 32] + red[1][t + 32] + red[2][t + 32] + red[3][t + 32];
        float ss = x0 * x0 + x1 * x1;
#pragma unroll
        for (int o = 16; o > 0; o >>= 1)
            ss += __shfl_xor_sync(0xffffffffu, ss, o);
        float sc = (ss > 0.f) ? (ss / (1.f + ss)) * rsqrtf(ss) : 0.f;
        float o0 = sc * x0, o1 = sc * x1;
        if (mode == 0) {
            g_v0[vec * QQ + t] = o0;
            g_v0[vec * QQ + 32 + t] = o1;
        } else if (mode == 1) {
            g_v01[vec * QQ + t] = g_v0[vec * QQ + t] + o0;
            g_v01[vec * QQ + 32 + t] = g_v0[vec * QQ + 32 + t] + o1;
        } else {
            dout[vec * QQ + t] = o0;
            dout[vec * QQ + 32 + t] = o1;
        }
    }
}

// ---------------- launch ----------------
extern "C" void kernel_launch(void* const* d_in, const int* in_sizes, int n_in,
                              void* d_out, int out_size) {
    const float* x = (const float*)d_in[0];     // [32,1152,64]
    const float* W = (const float*)d_in[1];     // [1152,32,64,64]
    const float* bias = (const float*)d_in[2];  // [1,1152,32,1]
    float* out = (float*)d_out;                 // [32,32,64]

    static int smem_set = 0;
    if (!smem_set) {
        cudaFuncSetAttribute(gemm_kernel, cudaFuncAttributeMaxDynamicSharedMemorySize,
                             GEMM_SMEM_BYTES);
        cudaFuncSetAttribute(route_kernel, cudaFuncAttributeMaxDynamicSharedMemorySize,
                             RT_SMEM_BYTES);
        smem_set = 1;
    }

    gemm_kernel<<<dim3(NC / 2, NIBLK), 128, GEMM_SMEM_BYTES>>>(x, W, bias);
    reduce_squash_kernel<<<BB * NC, 256>>>(0, out);
    route_kernel<<<dim3(NRBLK, BB), 256, RT_SMEM_BYTES>>>(1, bias);
    reduce_squash_kernel<<<BB * NC, 256>>>(1, out);
    route_kernel<<<dim3(NRBLK, BB), 256, RT_SMEM_BYTES>>>(2, bias);
    reduce_squash_kernel<<<BB * NC, 256>>>(2, out);
}